// round 6
// baseline (speedup 1.0000x reference)
#include <cuda_runtime.h>
#include <cuda_fp16.h>

#define HH 200
#define WW 320
#define CC 256
#define HWSZ (HH * WW)
#define RS 14
#define BINS (RS * RS)

// Scratch: transposed feature [H][W][C] fp16, per-pixel channel max (ordered
// uint), per-bin maxima. No init kernel needed: g_M and g_bins are fully
// written by transposeM / boundseed before anyone reads them.
__device__ __align__(128) static __half g_featT[(size_t)HWSZ * CC];
__device__ static unsigned g_M[HWSZ];
__device__ static unsigned g_bins[BINS];

__device__ __forceinline__ unsigned enc_f(float f) {
    unsigned u = __float_as_uint(f);
    return (u & 0x80000000u) ? ~u : (u | 0x80000000u);
}
__device__ __forceinline__ float dec_f(unsigned u) {
    return __uint_as_float((u & 0x80000000u) ? (u ^ 0x80000000u) : ~u);
}

// Transpose feature [C][H*W] fp32 -> [H*W][C] fp16 AND finish the per-pixel
// channel max in-block (loops all 4 chunks of 64 channels). Plain stores only.
__global__ void transposeM_kernel(const float* __restrict__ A) {
    __shared__ float tile[64][33];
    int hw0 = blockIdx.x * 32;
    int tx = threadIdx.x, ty = threadIdx.y;  // 32 x 8
    float pmax[4];
#pragma unroll
    for (int rr = 0; rr < 4; rr++) pmax[rr] = __int_as_float(0xff800000);

#pragma unroll
    for (int cb = 0; cb < 4; cb++) {
        int c0 = cb * 64;
#pragma unroll
        for (int j = 0; j < 64; j += 8)
            tile[ty + j][tx] = A[(size_t)(c0 + ty + j) * HWSZ + hw0 + tx];
        __syncthreads();
#pragma unroll
        for (int rr = 0; rr < 4; rr++) {
            int hwr = ty + rr * 8;
            __half2 h = __floats2half2_rn(tile[2 * tx][hwr], tile[2 * tx + 1][hwr]);
            ((__half2*)(g_featT + (size_t)(hw0 + hwr) * CC + c0))[tx] = h;
            float2 f = __half22float2(h);
            pmax[rr] = fmaxf(pmax[rr], fmaxf(f.x, f.y));
        }
        __syncthreads();
    }
#pragma unroll
    for (int rr = 0; rr < 4; rr++) {
        float v = pmax[rr];
#pragma unroll
        for (int o = 16; o; o >>= 1)
            v = fmaxf(v, __shfl_xor_sync(0xffffffffu, v, o));
        if (tx == 0) g_M[hw0 + ty + rr * 8] = enc_f(v);
    }
}

// Convex-interp upper bound on max_c bilinear_c at (y, x). Sound because all
// weights are in [0,1] and sum to 1 (samples interior). +1e-3 absolute margin
// absorbs fp ordering differences between bound and exact paths.
__device__ __forceinline__ float sample_bound(float y, float x) {
    int yf = (int)floorf(y), xf = (int)floorf(x);
    int y1 = min(max(yf, 0), HH - 1);
    int y2 = min(max(yf + 1, 0), HH - 1);
    int x1 = min(max(xf, 0), WW - 1);
    int x2 = min(max(xf + 1, 0), WW - 1);
    float wxl = x - (float)x1, wxh = (float)x2 - x;
    float wyl = y - (float)y1, wyh = (float)y2 - y;
    float m11 = dec_f(g_M[y1 * WW + x1]);
    float m12 = dec_f(g_M[y1 * WW + x2]);
    float m21 = dec_f(g_M[y2 * WW + x1]);
    float m22 = dec_f(g_M[y2 * WW + x2]);
    return (m11 * wxh + m12 * wxl) * wyh + (m21 * wxh + m22 * wxl) * wyl + 1e-3f;
}

// Exact per-lane partial: lane covers 8 channels (one uint4 of fp16).
__device__ __forceinline__ float sample_exact_lane(float y, float x, int lane) {
    int yf = (int)floorf(y), xf = (int)floorf(x);
    int y1 = min(max(yf, 0), HH - 1);
    int y2 = min(max(yf + 1, 0), HH - 1);
    int x1 = min(max(xf, 0), WW - 1);
    int x2 = min(max(xf + 1, 0), WW - 1);
    float wxl = x - (float)x1, wxh = (float)x2 - x;
    float wyl = y - (float)y1, wyh = (float)y2 - y;
    const uint4* p11 = (const uint4*)(g_featT + (size_t)(y1 * WW + x1) * CC);
    const uint4* p12 = (const uint4*)(g_featT + (size_t)(y1 * WW + x2) * CC);
    const uint4* p21 = (const uint4*)(g_featT + (size_t)(y2 * WW + x1) * CC);
    const uint4* p22 = (const uint4*)(g_featT + (size_t)(y2 * WW + x2) * CC);
    uint4 A = p11[lane];
    uint4 B = p12[lane];
    uint4 C = p21[lane];
    uint4 D = p22[lane];
    float vmax = __int_as_float(0xff800000);
#pragma unroll
    for (int k = 0; k < 4; k++) {
        float2 fa = __half22float2(*(const __half2*)(&((const unsigned*)&A)[k]));
        float2 fb = __half22float2(*(const __half2*)(&((const unsigned*)&B)[k]));
        float2 fc = __half22float2(*(const __half2*)(&((const unsigned*)&C)[k]));
        float2 fd = __half22float2(*(const __half2*)(&((const unsigned*)&D)[k]));
        float v0 = (fa.x * wxh + fb.x * wxl) * wyh + (fc.x * wxh + fd.x * wxl) * wyl;
        float v1 = (fa.y * wxh + fb.y * wxl) * wyh + (fc.y * wxh + fd.y * wxl) * wyl;
        vmax = fmaxf(vmax, fmaxf(v0, v1));
    }
    return vmax;
}

__device__ __forceinline__ void coords_from(const float* __restrict__ roi4,
                                            int m, int n, int pt,
                                            float* y_out, float* x_out) {
    float sh = (roi4[2] - roi4[0]) / (float)RS;
    float sw = (roi4[3] - roi4[1]) / (float)RS;
    float fy = (pt >> 1) ? (2.0f / 3.0f) : (1.0f / 3.0f);
    float fx = (pt & 1) ? (2.0f / 3.0f) : (1.0f / 3.0f);
    *y_out = (roi4[0] + sh * (float)m) + sh * fy;
    *x_out = (roi4[1] + sw * (float)n) + sw * fx;
}

// One block per bin: compute bound U for all R*4 samples of this bin, find the
// block-wide argmax(U), exactly evaluate that ONE sample (warp 0) and plain-
// store it as the bin's lower bound L. No atomics, no init dependencies.
__global__ void boundseed_kernel(const float* __restrict__ rois, int R) {
    __shared__ float sroi[512];                 // up to R=128 rois
    __shared__ unsigned long long wred[8];
    int mn = blockIdx.x;
    int m = mn / RS, n = mn - m * RS;
    int t = threadIdx.x;
    int lane = t & 31, warp = t >> 5;

    for (int i = t; i < 4 * R; i += 256) sroi[i] = rois[i];
    __syncthreads();

    unsigned long long best = 0ull;
    for (int s = t; s < 4 * R; s += 256) {
        int r = s >> 2, pt = s & 3;
        float y, x;
        coords_from(sroi + 4 * r, m, n, pt, &y, &x);
        float U = sample_bound(y, x);
        unsigned long long p = ((unsigned long long)enc_f(U) << 32) | (unsigned)s;
        best = best > p ? best : p;
    }
#pragma unroll
    for (int o = 16; o; o >>= 1) {
        unsigned long long ot = __shfl_xor_sync(0xffffffffu, best, o);
        best = best > ot ? best : ot;
    }
    if (lane == 0) wred[warp] = best;
    __syncthreads();
    if (warp == 0) {
        unsigned long long b = (lane < 8) ? wred[lane] : 0ull;
#pragma unroll
        for (int o = 4; o; o >>= 1) {
            unsigned long long ot = __shfl_xor_sync(0xffffffffu, b, o);
            b = b > ot ? b : ot;
        }
        b = __shfl_sync(0xffffffffu, b, 0);
        int s = (int)(unsigned)(b & 0xffffffffull);
        int r = s >> 2, pt = s & 3;
        float y, x;
        coords_from(sroi + 4 * r, m, n, pt, &y, &x);
        float v = sample_exact_lane(y, x, lane);
#pragma unroll
        for (int o = 16; o; o >>= 1)
            v = fmaxf(v, __shfl_xor_sync(0xffffffffu, v, o));
        if (lane == 0) g_bins[mn] = enc_f(v);
    }
}

// Warp per (roi, bin): skip any sample whose bound <= current bin L.
__global__ void prune_exact_kernel(const float* __restrict__ rois, int R) {
    int warp = threadIdx.x >> 5;
    int lane = threadIdx.x & 31;
    int wid = blockIdx.x * (blockDim.x >> 5) + warp;
    if (wid >= R * BINS) return;
    int r = wid / BINS;
    int mn = wid - r * BINS;
    int m = mn / RS;
    int n = mn - m * RS;

    float r0 = __ldg(rois + 4 * r + 0);
    float r1 = __ldg(rois + 4 * r + 1);
    float r2 = __ldg(rois + 4 * r + 2);
    float r3 = __ldg(rois + 4 * r + 3);
    float sh = (r2 - r0) / (float)RS;
    float sw = (r3 - r1) / (float)RS;
    float yb = r0 + sh * (float)m;
    float xb = r1 + sw * (float)n;
    float ys[2] = {yb + sh * (1.0f / 3.0f), yb + sh * (2.0f / 3.0f)};
    float xs[2] = {xb + sw * (1.0f / 3.0f), xb + sw * (2.0f / 3.0f)};

    float vmax = __int_as_float(0xff800000);
    bool any = false;
#pragma unroll
    for (int pt = 0; pt < 4; pt++) {
        float y = ys[pt >> 1], x = xs[pt & 1];
        float L = dec_f(__ldcg(&g_bins[mn]));  // fresh L -> better pruning
        float U = sample_bound(y, x);
        if (U > L) {
            vmax = fmaxf(vmax, sample_exact_lane(y, x, lane));
            any = true;
        }
    }
    if (__any_sync(0xffffffffu, any)) {
#pragma unroll
        for (int o = 16; o; o >>= 1)
            vmax = fmaxf(vmax, __shfl_xor_sync(0xffffffffu, vmax, o));
        if (lane == 0) atomicMax(&g_bins[mn], enc_f(vmax));
    }
}

// Broadcast: grid*block (in float4 units) == 0 mod 49, so each thread's bin
// value is constant across iterations: one smem read, pure STG.128 loop.
__global__ void bcast_kernel(float* __restrict__ out, int total4) {
    __shared__ float4 s4[49];
    int t = threadIdx.x;
    if (t < BINS) ((float*)s4)[t] = dec_f(g_bins[t]);
    __syncthreads();
    int g0 = blockIdx.x * blockDim.x + t;
    float4 v = s4[g0 % 49];
    int stride = blockDim.x * gridDim.x;  // 931*256 = 49*4864
#pragma unroll 7
    for (int g = g0; g < total4; g += stride)
        ((float4*)out)[g] = v;
}

extern "C" void kernel_launch(void* const* d_in, const int* in_sizes, int n_in,
                              void* d_out, int out_size) {
    const float* feature = (const float*)d_in[0];
    const float* rois = (const float*)d_in[1];
    int R = in_sizes[1] / 4;
    if (R > 128) R = 128;

    dim3 tb(32, 8);
    transposeM_kernel<<<HWSZ / 32, tb>>>(feature);

    boundseed_kernel<<<BINS, 256>>>(rois, R);

    int warps = R * BINS;
    prune_exact_kernel<<<(warps + 7) / 8, 256>>>(rois, R);

    int total4 = out_size / 4;
    bcast_kernel<<<931, 256>>>((float*)d_out, total4);
}

// round 7
// speedup vs baseline: 1.3194x; 1.3194x over previous
#include <cuda_runtime.h>
#include <cuda_fp16.h>

#define HH 200
#define WW 320
#define CC 256
#define HWSZ (HH * WW)
#define RS 14
#define BINS (RS * RS)

// featT: [H*W][C] fp16. g_Mg: per-pixel per-group (8 groups x 32ch) maxima,
// fp16, 16B per pixel. g_bins: per-bin maxima (ordered-uint encoded).
__device__ __align__(128) static __half g_featT[(size_t)HWSZ * CC];
__device__ __align__(128) static __half g_Mg[(size_t)HWSZ * 8];
__device__ static unsigned g_bins[BINS];

__device__ __forceinline__ unsigned enc_f(float f) {
    unsigned u = __float_as_uint(f);
    return (u & 0x80000000u) ? ~u : (u | 0x80000000u);
}
__device__ __forceinline__ float dec_f(unsigned u) {
    return __uint_as_float((u & 0x80000000u) ? (u ^ 0x80000000u) : ~u);
}
#define ENC_NEG_INF 0x007FFFFFu  // enc_f(-inf)

// Transpose feature [C][H*W] fp32 -> featT [H*W][C] fp16 (R3 shape: 8000
// independent blocks, 64ch x 32hw tiles) AND emit per-pixel 32-channel group
// maxima (this block covers groups 2*by and 2*by+1 -> plain stores, no
// atomics). Block (0,0) also initializes g_bins (kills the init launch).
__global__ void transpose_kernel(const float* __restrict__ A) {
    __shared__ float tile[64][33];
    int hw0 = blockIdx.x * 32;
    int c0 = blockIdx.y * 64;
    int tx = threadIdx.x, ty = threadIdx.y;  // 32 x 8

    if (blockIdx.x == 0 && blockIdx.y == 0) {
        int t = ty * 32 + tx;
        if (t < BINS) g_bins[t] = ENC_NEG_INF;
    }

#pragma unroll
    for (int j = 0; j < 64; j += 8)
        tile[ty + j][tx] = A[(size_t)(c0 + ty + j) * HWSZ + hw0 + tx];
    __syncthreads();
    // warp ty handles hw rows ty+8*rr; lane tx = channel pair (c0+2tx, c0+2tx+1)
#pragma unroll
    for (int rr = 0; rr < 4; rr++) {
        int hwr = ty + rr * 8;
        __half2 h = __floats2half2_rn(tile[2 * tx][hwr], tile[2 * tx + 1][hwr]);
        ((__half2*)(g_featT + (size_t)(hw0 + hwr) * CC + c0))[tx] = h;
        // group max: lanes 0-15 = channels c0..c0+31, lanes 16-31 = c0+32..c0+63
        float2 f = __half22float2(h);
        float v = fmaxf(f.x, f.y);
#pragma unroll
        for (int o = 8; o; o >>= 1)
            v = fmaxf(v, __shfl_xor_sync(0xffffffffu, v, o));  // stays in half-warp
        int pix = hw0 + hwr;
        if (tx == 0) g_Mg[(size_t)pix * 8 + blockIdx.y * 2] = __float2half_rn(v);
        if (tx == 16) g_Mg[(size_t)pix * 8 + blockIdx.y * 2 + 1] = __float2half_rn(v);
    }
}

// One warp per (roi, bin). Lane covers channels [8*lane, 8*lane+8) = group
// lane>>2. Per sample: lane checks ITS group's convex-interp bound against the
// running bin max; only surviving lanes issue the 4 corner LDG.128s.
__global__ void roi_max_kernel(const float* __restrict__ rois, int R) {
    int warp = threadIdx.x >> 5;
    int lane = threadIdx.x & 31;
    int wid = blockIdx.x * (blockDim.x >> 5) + warp;
    if (wid >= R * BINS) return;
    int r = wid / BINS;
    int mn = wid - r * BINS;
    int m = mn / RS;
    int n = mn - m * RS;
    int g = lane >> 2;

    float r0 = __ldg(rois + 4 * r + 0);
    float r1 = __ldg(rois + 4 * r + 1);
    float r2 = __ldg(rois + 4 * r + 2);
    float r3 = __ldg(rois + 4 * r + 3);
    float sh = (r2 - r0) / (float)RS;
    float sw = (r3 - r1) / (float)RS;
    float yb = r0 + sh * (float)m;
    float xb = r1 + sw * (float)n;
    float ys[2] = {yb + sh * (1.0f / 3.0f), yb + sh * (2.0f / 3.0f)};
    float xs[2] = {xb + sw * (1.0f / 3.0f), xb + sw * (2.0f / 3.0f)};

    float vmax = __int_as_float(0xff800000);  // -inf
    bool any = false;

#pragma unroll
    for (int pt = 0; pt < 4; pt++) {
        float y = ys[pt >> 1], x = xs[pt & 1];
        int yf = (int)floorf(y);
        int xf = (int)floorf(x);
        // clamp BEFORE weights (faithful to reference)
        int y1 = min(max(yf, 0), HH - 1);
        int y2 = min(max(yf + 1, 0), HH - 1);
        int x1 = min(max(xf, 0), WW - 1);
        int x2 = min(max(xf + 1, 0), WW - 1);
        float wxl = x - (float)x1, wxh = (float)x2 - x;
        float wyl = y - (float)y1, wyh = (float)y2 - y;
        int pix11 = y1 * WW + x1;
        int pix12 = y1 * WW + x2;
        int pix21 = y2 * WW + x1;
        int pix22 = y2 * WW + x2;

        // Running bin max (L2-fresh; stale only weakens pruning, stays sound)
        float L = dec_f(__ldcg(&g_bins[mn]));
        // This lane's group bound: convex interp of the 4 corner group maxima
        float m11 = __half2float(__ldg(&g_Mg[(size_t)pix11 * 8 + g]));
        float m12 = __half2float(__ldg(&g_Mg[(size_t)pix12 * 8 + g]));
        float m21 = __half2float(__ldg(&g_Mg[(size_t)pix21 * 8 + g]));
        float m22 = __half2float(__ldg(&g_Mg[(size_t)pix22 * 8 + g]));
        float bg = (m11 * wxh + m12 * wxl) * wyh + (m21 * wxh + m22 * wxl) * wyl;

        if (bg + 1e-4f > L) {
            const uint4* p11 = (const uint4*)(g_featT + (size_t)pix11 * CC);
            const uint4* p12 = (const uint4*)(g_featT + (size_t)pix12 * CC);
            const uint4* p21 = (const uint4*)(g_featT + (size_t)pix21 * CC);
            const uint4* p22 = (const uint4*)(g_featT + (size_t)pix22 * CC);
            uint4 A = p11[lane];
            uint4 B = p12[lane];
            uint4 C = p21[lane];
            uint4 D = p22[lane];
#pragma unroll
            for (int k = 0; k < 4; k++) {
                float2 fa = __half22float2(*(const __half2*)(&((const unsigned*)&A)[k]));
                float2 fb = __half22float2(*(const __half2*)(&((const unsigned*)&B)[k]));
                float2 fc = __half22float2(*(const __half2*)(&((const unsigned*)&C)[k]));
                float2 fd = __half22float2(*(const __half2*)(&((const unsigned*)&D)[k]));
                float v0 = (fa.x * wxh + fb.x * wxl) * wyh + (fc.x * wxh + fd.x * wxl) * wyl;
                float v1 = (fa.y * wxh + fb.y * wxl) * wyh + (fc.y * wxh + fd.y * wxl) * wyl;
                vmax = fmaxf(vmax, fmaxf(v0, v1));
            }
            any = true;
        }
    }

    if (__any_sync(0xffffffffu, any)) {
#pragma unroll
        for (int o = 16; o; o >>= 1)
            vmax = fmaxf(vmax, __shfl_xor_sync(0xffffffffu, vmax, o));
        if (lane == 0) atomicMax(&g_bins[mn], enc_f(vmax));
    }
}

// Broadcast: grid*block (in float4 units) == 0 mod 49, so each thread's value
// is constant across iterations: one smem read, then pure STG.128 loop.
__global__ void bcast_kernel(float* __restrict__ out, int total4) {
    __shared__ float4 s4[49];
    int t = threadIdx.x;
    if (t < BINS) ((float*)s4)[t] = dec_f(g_bins[t]);
    __syncthreads();
    int g0 = blockIdx.x * blockDim.x + t;
    float4 v = s4[g0 % 49];
    int stride = blockDim.x * gridDim.x;  // 931*256 = 49*4864
    for (int g = g0; g < total4; g += stride)
        ((float4*)out)[g] = v;
}

extern "C" void kernel_launch(void* const* d_in, const int* in_sizes, int n_in,
                              void* d_out, int out_size) {
    const float* feature = (const float*)d_in[0];
    const float* rois = (const float*)d_in[1];
    int R = in_sizes[1] / 4;

    dim3 tb(32, 8);
    dim3 tg(HWSZ / 32, CC / 64);
    transpose_kernel<<<tg, tb>>>(feature);

    int warps = R * BINS;
    roi_max_kernel<<<(warps + 7) / 8, 256>>>(rois, R);

    int total4 = out_size / 4;
    bcast_kernel<<<931, 256>>>((float*)d_out, total4);
}

// round 8
// speedup vs baseline: 1.4204x; 1.0766x over previous
#include <cuda_runtime.h>
#include <cuda_fp16.h>

#define HH 200
#define WW 320
#define CC 256
#define HWSZ (HH * WW)
#define RS 14
#define BINS (RS * RS)

// featT: [H*W][C] fp16. g_Mg: per-pixel per-group (8 groups x 32ch) maxima,
// fp16, 16B per pixel. g_bins: per-bin maxima (ordered-uint encoded).
__device__ __align__(128) static __half g_featT[(size_t)HWSZ * CC];
__device__ __align__(128) static __half g_Mg[(size_t)HWSZ * 8];
__device__ static unsigned g_bins[BINS];

__device__ __forceinline__ unsigned enc_f(float f) {
    unsigned u = __float_as_uint(f);
    return (u & 0x80000000u) ? ~u : (u | 0x80000000u);
}
__device__ __forceinline__ float dec_f(unsigned u) {
    return __uint_as_float((u & 0x80000000u) ? (u ^ 0x80000000u) : ~u);
}
#define ENC_NEG_INF 0x007FFFFFu  // enc_f(-inf)

// Transpose feature [C][H*W] fp32 -> featT [H*W][C] fp16 (8000 independent
// blocks, 64ch x 32hw tiles). Per-pixel 32-channel group maxima are computed
// by threads 0..63 reading tile COLUMNS via LDS (conflict-free; tile is
// stable after the first sync) -- no shuffles, no atomics.
// Block (0,0) also initializes g_bins (kills the init launch).
__global__ void transpose_kernel(const float* __restrict__ A) {
    __shared__ float tile[64][33];
    int hw0 = blockIdx.x * 32;
    int c0 = blockIdx.y * 64;
    int tx = threadIdx.x, ty = threadIdx.y;  // 32 x 8
    int t = ty * 32 + tx;

    if (blockIdx.x == 0 && blockIdx.y == 0 && t < BINS)
        g_bins[t] = ENC_NEG_INF;

#pragma unroll
    for (int j = 0; j < 64; j += 8)
        tile[ty + j][tx] = A[(size_t)(c0 + ty + j) * HWSZ + hw0 + tx];
    __syncthreads();

    // Main transpose stores: warp ty covers hw rows ty+8*rr; lane tx = ch pair
#pragma unroll
    for (int rr = 0; rr < 4; rr++) {
        int hwr = ty + rr * 8;
        __half2 h = __floats2half2_rn(tile[2 * tx][hwr], tile[2 * tx + 1][hwr]);
        ((__half2*)(g_featT + (size_t)(hw0 + hwr) * CC + c0))[tx] = h;
    }

    // Group maxima: threads 0..63, task = (pixel tx, subgroup t>>5).
    // Row read tile[k][pix] is conflict-free across lanes (consecutive floats).
    if (t < 64) {
        int pix = t & 31;
        int sub = t >> 5;
        float v = __int_as_float(0xff800000);
#pragma unroll
        for (int k = 0; k < 32; k++)
            v = fmaxf(v, tile[sub * 32 + k][pix]);
        // rn is monotone: rn(max) >= rn(c) for every channel c in the group,
        // so this fp16 value is a sound bound on the fp16 featT entries.
        g_Mg[(size_t)(hw0 + pix) * 8 + blockIdx.y * 2 + sub] = __float2half_rn(v);
    }
}

// One warp per (roi, bin). Lane covers channels [8*lane, 8*lane+8) = group
// lane>>2. Per sample: lane checks ITS group's convex-interp bound against the
// running bin max; only surviving lanes issue the 4 corner LDG.128s.
__global__ void roi_max_kernel(const float* __restrict__ rois, int R) {
    int warp = threadIdx.x >> 5;
    int lane = threadIdx.x & 31;
    int wid = blockIdx.x * (blockDim.x >> 5) + warp;
    if (wid >= R * BINS) return;
    int r = wid / BINS;
    int mn = wid - r * BINS;
    int m = mn / RS;
    int n = mn - m * RS;
    int g = lane >> 2;

    float r0 = __ldg(rois + 4 * r + 0);
    float r1 = __ldg(rois + 4 * r + 1);
    float r2 = __ldg(rois + 4 * r + 2);
    float r3 = __ldg(rois + 4 * r + 3);
    float sh = (r2 - r0) / (float)RS;
    float sw = (r3 - r1) / (float)RS;
    float yb = r0 + sh * (float)m;
    float xb = r1 + sw * (float)n;
    float ys[2] = {yb + sh * (1.0f / 3.0f), yb + sh * (2.0f / 3.0f)};
    float xs[2] = {xb + sw * (1.0f / 3.0f), xb + sw * (2.0f / 3.0f)};

    // Running bin max, read ONCE per warp (stale only weakens pruning).
    float L = dec_f(__ldcg(&g_bins[mn]));

    float vmax = __int_as_float(0xff800000);  // -inf
    bool any = false;

#pragma unroll
    for (int pt = 0; pt < 4; pt++) {
        float y = ys[pt >> 1], x = xs[pt & 1];
        int yf = (int)floorf(y);
        int xf = (int)floorf(x);
        // clamp BEFORE weights (faithful to reference)
        int y1 = min(max(yf, 0), HH - 1);
        int y2 = min(max(yf + 1, 0), HH - 1);
        int x1 = min(max(xf, 0), WW - 1);
        int x2 = min(max(xf + 1, 0), WW - 1);
        float wxl = x - (float)x1, wxh = (float)x2 - x;
        float wyl = y - (float)y1, wyh = (float)y2 - y;
        int pix11 = y1 * WW + x1;
        int pix12 = y1 * WW + x2;
        int pix21 = y2 * WW + x1;
        int pix22 = y2 * WW + x2;

        // This lane's group bound: convex interp of the 4 corner group maxima
        float m11 = __half2float(__ldg(&g_Mg[(size_t)pix11 * 8 + g]));
        float m12 = __half2float(__ldg(&g_Mg[(size_t)pix12 * 8 + g]));
        float m21 = __half2float(__ldg(&g_Mg[(size_t)pix21 * 8 + g]));
        float m22 = __half2float(__ldg(&g_Mg[(size_t)pix22 * 8 + g]));
        float bg = (m11 * wxh + m12 * wxl) * wyh + (m21 * wxh + m22 * wxl) * wyl;

        if (bg + 1e-4f > L) {
            const uint4* p11 = (const uint4*)(g_featT + (size_t)pix11 * CC);
            const uint4* p12 = (const uint4*)(g_featT + (size_t)pix12 * CC);
            const uint4* p21 = (const uint4*)(g_featT + (size_t)pix21 * CC);
            const uint4* p22 = (const uint4*)(g_featT + (size_t)pix22 * CC);
            uint4 A = p11[lane];
            uint4 B = p12[lane];
            uint4 C = p21[lane];
            uint4 D = p22[lane];
#pragma unroll
            for (int k = 0; k < 4; k++) {
                float2 fa = __half22float2(*(const __half2*)(&((const unsigned*)&A)[k]));
                float2 fb = __half22float2(*(const __half2*)(&((const unsigned*)&B)[k]));
                float2 fc = __half22float2(*(const __half2*)(&((const unsigned*)&C)[k]));
                float2 fd = __half22float2(*(const __half2*)(&((const unsigned*)&D)[k]));
                float v0 = (fa.x * wxh + fb.x * wxl) * wyh + (fc.x * wxh + fd.x * wxl) * wyl;
                float v1 = (fa.y * wxh + fb.y * wxl) * wyh + (fc.y * wxh + fd.y * wxl) * wyl;
                vmax = fmaxf(vmax, fmaxf(v0, v1));
            }
            any = true;
        }
    }

    if (__any_sync(0xffffffffu, any)) {
#pragma unroll
        for (int o = 16; o; o >>= 1)
            vmax = fmaxf(vmax, __shfl_xor_sync(0xffffffffu, vmax, o));
        if (lane == 0) atomicMax(&g_bins[mn], enc_f(vmax));
    }
}

// Broadcast bin_max to out[R][C][14][14]. Each thread does 4 warp-contiguous
// float4 stores (block tile = 1024 float4s; store k at g0 + 256k keeps every
// STG.128 512B-contiguous per warp). Bin index advances by 11 mod 49 per k.
__global__ void bcast_kernel(float* __restrict__ out, int total4) {
    __shared__ float4 s4[49];
    int t = threadIdx.x;
    if (t < BINS) ((float*)s4)[t] = dec_f(g_bins[t]);
    __syncthreads();
    int g0 = blockIdx.x * 1024 + t;
    int mq = g0 % 49;  // 256 mod 49 == 11
#pragma unroll
    for (int k = 0; k < 4; k++) {
        int g = g0 + k * 256;
        if (g < total4) ((float4*)out)[g] = s4[mq];
        mq += 11;
        if (mq >= 49) mq -= 49;
    }
}

extern "C" void kernel_launch(void* const* d_in, const int* in_sizes, int n_in,
                              void* d_out, int out_size) {
    const float* feature = (const float*)d_in[0];
    const float* rois = (const float*)d_in[1];
    int R = in_sizes[1] / 4;

    dim3 tb(32, 8);
    dim3 tg(HWSZ / 32, CC / 64);
    transpose_kernel<<<tg, tb>>>(feature);

    int warps = R * BINS;
    roi_max_kernel<<<(warps + 7) / 8, 256>>>(rois, R);

    int total4 = out_size / 4;
    bcast_kernel<<<(total4 + 1023) / 1024, 256>>>((float*)d_out, total4);
}